// round 12
// baseline (speedup 1.0000x reference)
#include <cuda_runtime.h>
#include <cuda_fp16.h>
#include <cstdint>
#include <cstddef>

// ---------------------------------------------------------------------------
// GlobalFeatureMoE: AdaLN + top-2 MoE (8 routed + 1 shared expert) + residual
// fp16 mma.sync.m16n8k16 (fp32 accum), 128x128xBK64 tiles, 3-stage cp.async,
// 2 CTAs/SM, smem-restaged coalesced epilogues.
// R9 fix: fp16 epilogue restage row stride 264 -> 272 (16B-aligned float4 reads)
// ---------------------------------------------------------------------------

constexpr int TKN  = 8192;   // B*L
constexpr int DIM  = 1024;
constexpr int NEXP = 8;
constexpr int HID  = 4096;
constexpr int NBATCH = 4;
constexpr int SEQ  = 2048;

constexpr int BM = 128, BN = 128, BK = 64, NSTAGE = 3;
constexpr int STAGE = 32768;               // A 16KB (4 x 4KB k16-blocks) + B 16KB
constexpr int SMEM_BYTES = NSTAGE * STAGE; // 98304 -> 2 CTAs/SM (192KB/SM)

// scratch (static __device__ arrays — allocation-free per harness rules)
__device__ float  g_cond[NBATCH * 2 * DIM];
__device__ int    g_cnt[NEXP];
__device__ int    g_idx[NEXP * TKN];
__device__ int    g_re[2 * TKN];
__device__ int    g_rs[2 * TKN];
__device__ float  g_rw[2 * TKN];
__device__ __half g_xnh[(size_t)TKN * DIM];          // fp16 normalized tokens
__device__ __half g_hf [(size_t)9 * TKN * HID];      // fp16 hidden per bucket
__device__ float  g_o2 [(size_t)9 * TKN * DIM];      // fp32 expert outputs
__device__ __half g_w1h[(size_t)NEXP * DIM * HID];
__device__ __half g_w2h[(size_t)NEXP * HID * DIM];
__device__ __half g_sw1h[(size_t)DIM * HID];
__device__ __half g_sw2h[(size_t)HID * DIM];

// ---------------------------------------------------------------------------
__device__ __forceinline__ uint32_t smem_u32(const void* p) {
    uint32_t a;
    asm("{ .reg .u64 t; cvta.to.shared.u64 t, %1; cvt.u32.u64 %0, t; }" : "=r"(a) : "l"(p));
    return a;
}
#define CP_ASYNC16(dst, src) \
    asm volatile("cp.async.cg.shared.global [%0], [%1], 16;" :: "r"(dst), "l"(src))
#define CP_COMMIT() asm volatile("cp.async.commit_group;" ::: "memory")
#define CP_WAIT(n)  asm volatile("cp.async.wait_group %0;" :: "n"(n) : "memory")

#define LDSM_X4(r, addr) \
    asm volatile("ldmatrix.sync.aligned.m8n8.x4.shared.b16 {%0,%1,%2,%3}, [%4];" \
        : "=r"((r)[0]), "=r"((r)[1]), "=r"((r)[2]), "=r"((r)[3]) : "r"(addr))
#define LDSM_X4T(r, addr) \
    asm volatile("ldmatrix.sync.aligned.m8n8.x4.trans.shared.b16 {%0,%1,%2,%3}, [%4];" \
        : "=r"((r)[0]), "=r"((r)[1]), "=r"((r)[2]), "=r"((r)[3]) : "r"(addr))

__device__ __forceinline__ void mma_f16(float* c, const uint32_t* a, const uint32_t* b) {
    asm volatile(
        "mma.sync.aligned.m16n8k16.row.col.f32.f16.f16.f32 "
        "{%0,%1,%2,%3}, {%4,%5,%6,%7}, {%8,%9}, {%0,%1,%2,%3};\n"
        : "+f"(c[0]), "+f"(c[1]), "+f"(c[2]), "+f"(c[3])
        : "r"(a[0]), "r"(a[1]), "r"(a[2]), "r"(a[3]), "r"(b[0]), "r"(b[1]));
}

__device__ __forceinline__ float gelu_t(float v) {
    float u = 0.7978845608028654f * (v + 0.044715f * v * v * v);
    return 0.5f * v * (1.0f + tanhf(u));
}

// ---------------------------------------------------------------------------
__global__ void init_kernel() {
    if (threadIdx.x < NEXP) g_cnt[threadIdx.x] = 0;
}

// single-launch fp32 -> fp16 conversion of all four weight matrices
__global__ void f2h_all(const float4* __restrict__ w1, const float4* __restrict__ w2,
                        const float4* __restrict__ s1, const float4* __restrict__ s2,
                        uint2* __restrict__ o1, uint2* __restrict__ o2,
                        uint2* __restrict__ o3, uint2* __restrict__ o4) {
    constexpr long N1 = (long)NEXP * DIM * HID / 4;   // 8388608
    constexpr long NS = (long)DIM * HID / 4;          // 1048576
    long i = (long)blockIdx.x * blockDim.x + threadIdx.x;
    const float4* in; uint2* out; long j;
    if      (i < N1)           { in = w1; out = o1; j = i; }
    else if (i < 2 * N1)       { in = w2; out = o2; j = i - N1; }
    else if (i < 2 * N1 + NS)  { in = s1; out = o3; j = i - 2 * N1; }
    else if (i < 2 * N1 + 2*NS){ in = s2; out = o4; j = i - 2 * N1 - NS; }
    else return;
    float4 v = in[j];
    __half2 a = __floats2half2_rn(v.x, v.y);
    __half2 b = __floats2half2_rn(v.z, v.w);
    out[j] = make_uint2(*(uint32_t*)&a, *(uint32_t*)&b);
}

// cond = silu(time_c) @ ada_w + ada_b
__global__ void cond_kernel(const float* __restrict__ tc,
                            const float* __restrict__ aw,
                            const float* __restrict__ ab) {
    __shared__ float s[DIM];
    int b = blockIdx.y;
    for (int i = threadIdx.x; i < DIM; i += blockDim.x) {
        float v = tc[(size_t)b * DIM + i];
        s[i] = v / (1.0f + expf(-v));
    }
    __syncthreads();
    int col = blockIdx.x * blockDim.x + threadIdx.x;
    float acc = ab[col];
    #pragma unroll 8
    for (int k = 0; k < DIM; ++k)
        acc += s[k] * aw[(size_t)k * (2 * DIM) + col];
    g_cond[(size_t)b * (2 * DIM) + col] = acc;
}

// fused AdaLN + fp32 gate + top-2 routing; writes fp16 xn
__global__ void adaln_route(const float* __restrict__ x,
                            const float* __restrict__ gw) {
    int t   = blockIdx.x;
    int tid = threadIdx.x;
    int lane = tid & 31, wid = tid >> 5;
    int b = t / SEQ;

    float4 xv = reinterpret_cast<const float4*>(x + (size_t)t * DIM)[tid];
    float s  = xv.x + xv.y + xv.z + xv.w;
    float ss = xv.x*xv.x + xv.y*xv.y + xv.z*xv.z + xv.w*xv.w;
    #pragma unroll
    for (int o = 16; o > 0; o >>= 1) {
        s  += __shfl_down_sync(0xffffffffu, s,  o);
        ss += __shfl_down_sync(0xffffffffu, ss, o);
    }
    __shared__ float red[2][8];
    if (lane == 0) { red[0][wid] = s; red[1][wid] = ss; }
    __syncthreads();
    float mu = 0.f, m2 = 0.f;
    #pragma unroll
    for (int w = 0; w < 8; ++w) { mu += red[0][w]; m2 += red[1][w]; }
    mu *= (1.0f / DIM); m2 *= (1.0f / DIM);
    float rstd = rsqrtf(m2 - mu * mu + 1e-6f);

    float4 sh = reinterpret_cast<const float4*>(g_cond + (size_t)b*2*DIM)[tid];
    float4 sc = reinterpret_cast<const float4*>(g_cond + (size_t)b*2*DIM + DIM)[tid];
    float4 xn;
    xn.x = (xv.x - mu) * rstd * (1.0f + sc.x) + sh.x;
    xn.y = (xv.y - mu) * rstd * (1.0f + sc.y) + sh.y;
    xn.z = (xv.z - mu) * rstd * (1.0f + sc.z) + sh.z;
    xn.w = (xv.w - mu) * rstd * (1.0f + sc.w) + sh.w;
    {
        __half2 h01 = __floats2half2_rn(xn.x, xn.y);
        __half2 h23 = __floats2half2_rn(xn.z, xn.w);
        *(uint2*)(g_xnh + (size_t)t * DIM + tid * 4) =
            make_uint2(*(uint32_t*)&h01, *(uint32_t*)&h23);
    }

    // gate logits in exact fp32
    float l[8];
    #pragma unroll
    for (int e = 0; e < 8; ++e) l[e] = 0.f;
    int d = tid * 4;
    float xs[4] = {xn.x, xn.y, xn.z, xn.w};
    #pragma unroll
    for (int j = 0; j < 4; ++j) {
        const float* wr = gw + (size_t)(d + j) * NEXP;
        #pragma unroll
        for (int e = 0; e < 8; ++e) l[e] += xs[j] * wr[e];
    }
    #pragma unroll
    for (int e = 0; e < 8; ++e) {
        #pragma unroll
        for (int o = 16; o > 0; o >>= 1)
            l[e] += __shfl_down_sync(0xffffffffu, l[e], o);
    }
    __shared__ float lred[8][8];
    if (lane == 0) {
        #pragma unroll
        for (int e = 0; e < 8; ++e) lred[e][wid] = l[e];
    }
    __syncthreads();
    if (tid == 0) {
        float L[8];
        #pragma unroll
        for (int e = 0; e < 8; ++e) {
            float a = 0.f;
            for (int w = 0; w < 8; ++w) a += lred[e][w];
            L[e] = a;
        }
        float mx = L[0];
        for (int e = 1; e < 8; ++e) mx = fmaxf(mx, L[e]);
        float p[8];
        for (int e = 0; e < 8; ++e) p[e] = expf(L[e] - mx);
        int ia = 0; float va = p[0];
        for (int e = 1; e < 8; ++e) if (p[e] > va) { ia = e; va = p[e]; }
        int ib = -1; float vb = -1.f;
        for (int e = 0; e < 8; ++e) if (e != ia && p[e] > vb) { ib = e; vb = p[e]; }
        float inv = 1.0f / (va + vb);
        int sa = atomicAdd(&g_cnt[ia], 1);
        int sb = atomicAdd(&g_cnt[ib], 1);
        g_idx[ia * TKN + sa] = t;
        g_idx[ib * TKN + sb] = t;
        g_re[2*t]   = ia; g_rs[2*t]   = sa; g_rw[2*t]   = va * inv;
        g_re[2*t+1] = ib; g_rs[2*t+1] = sb; g_rw[2*t+1] = vb * inv;
    }
}

// ---------------------------------------------------------------------------
// fp16 GEMM: CTA 128x128xBK64, 8 warps (4m x 2n) of 32x64, 3-stage cp.async,
// 2 CTAs/SM.  blockIdx.z = expert (0..7 routed, 8 = shared)
// A smem (per stage): 4 k16-blocks of [128 rows][32B]; granule c of row r at
//   block*4096 + r*32 + ((c ^ ((r>>2)&1))<<4)
// B smem (per stage, base 16384): [64 k][256B]; granule g of row k at
//   k*256 + ((g ^ (k&7))<<4)
// ---------------------------------------------------------------------------
template <bool GATHER>   // true: xnh -> gelu(xW1+b1) = g_hf ; false: g_hf -> hW2+b2 = g_o2
__global__ __launch_bounds__(256, 2) void moe_hgemm(
    const __half* __restrict__ Wr, const __half* __restrict__ Ws,
    const float* __restrict__ br, const float* __restrict__ bs) {
    constexpr int NOUT = GATHER ? HID : DIM;
    constexpr int KD   = GATHER ? DIM : HID;
    constexpr int NKT  = KD / BK;

    extern __shared__ char smem[];
    const int e   = blockIdx.z;
    const int cnt = (e < NEXP) ? g_cnt[e] : TKN;
    const int m0  = blockIdx.y * BM;
    if (m0 >= cnt) return;
    const int n0  = blockIdx.x * BN;
    const __half* W    = (e < NEXP) ? Wr + (size_t)e * KD * NOUT : Ws;
    const float*  bias = (e < NEXP) ? br + (size_t)e * NOUT      : bs;
    const __half* Ah   = GATHER ? g_xnh : g_hf;

    const uint32_t sbase = smem_u32(smem);
    const int tid = threadIdx.x, lane = tid & 31, wid = tid >> 5;
    const int wm = wid >> 1, wn = wid & 1;

    // ---- staging: A row tid&127, 64B contiguous (half-pair ahalf), 4 granules
    const int arow = tid & 127, ahalf = tid >> 7;    // ahalf in {0,1}
    int gr_s = m0 + arow;
    long aidx;
    if (GATHER) aidx = (e < NEXP) ? ((gr_s < cnt) ? g_idx[e * TKN + gr_s] : 0) : gr_s;
    else        aidx = (long)e * TKN + gr_s;
    const char* aRow = (const char*)(Ah + (size_t)aidx * KD) + ahalf * 64;
    uint32_t aOff[4];
    #pragma unroll
    for (int q = 0; q < 4; ++q) {
        int blk = ahalf * 2 + (q >> 1);              // k16-block 0..3
        int c   = q & 1;                             // granule in block
        aOff[q] = (uint32_t)(blk * 4096 + arow * 32 + ((c ^ ((arow >> 2) & 1)) << 4));
    }
    // B: thread covers k-row bk0 = tid>>2, granules g0..g0+3 (64B contiguous)
    const int bk0 = tid >> 2;                        // 0..63
    const int gn0 = (tid & 3) * 4;                   // 0,4,8,12
    const char* bRow = (const char*)(W + (size_t)bk0 * NOUT + n0 + gn0 * 8);
    uint32_t bOff[4];
    #pragma unroll
    for (int c = 0; c < 4; ++c)
        bOff[c] = (uint32_t)(16384 + bk0 * 256 + (((gn0 + c) ^ (bk0 & 7)) << 4));
    const size_t bStride = (size_t)BK * NOUT * sizeof(__half);

    auto load_stage = [&](int kt) {
        uint32_t so = sbase + (uint32_t)((kt % NSTAGE) * STAGE);
        const char* as = aRow + (size_t)kt * (BK * 2);
        CP_ASYNC16(so + aOff[0], as);
        CP_ASYNC16(so + aOff[1], as + 16);
        CP_ASYNC16(so + aOff[2], as + 32);
        CP_ASYNC16(so + aOff[3], as + 48);
        const char* bsrc = bRow + (size_t)kt * bStride;
        CP_ASYNC16(so + bOff[0], bsrc);
        CP_ASYNC16(so + bOff[1], bsrc + 16);
        CP_ASYNC16(so + bOff[2], bsrc + 32);
        CP_ASYNC16(so + bOff[3], bsrc + 48);
        CP_COMMIT();
    };

    // ---- fragment addresses (stage-relative)
    const int rr = lane & 15, cc = lane >> 4;
    const uint32_t aswz = (uint32_t)((cc ^ ((rr >> 2) & 1)) << 4);
    uint32_t aAddr[2];
    #pragma unroll
    for (int mi = 0; mi < 2; ++mi)
        aAddr[mi] = (uint32_t)((wm * 32 + mi * 16 + rr) * 32) + aswz;
    const int kk = ((lane >> 3) & 1) * 8 + (lane & 7);
    const int j2 = lane >> 4;
    uint32_t bAddr[4];
    #pragma unroll
    for (int p = 0; p < 4; ++p)
        bAddr[p] = (uint32_t)(16384 + kk * 256 + (((wn * 8 + p * 2 + j2) ^ (lane & 7)) << 4));

    float acc[2][8][4];
    #pragma unroll
    for (int mi = 0; mi < 2; ++mi)
        #pragma unroll
        for (int ni = 0; ni < 8; ++ni)
            #pragma unroll
            for (int q = 0; q < 4; ++q) acc[mi][ni][q] = 0.f;

    load_stage(0); load_stage(1);

    for (int kt = 0; kt < NKT; ++kt) {
        CP_WAIT(1);
        __syncthreads();
        if (kt + 2 < NKT) load_stage(kt + 2); else CP_COMMIT();

        const uint32_t sA = sbase + (uint32_t)((kt % NSTAGE) * STAGE);
        #pragma unroll
        for (int s2 = 0; s2 < 4; ++s2) {
            uint32_t a[2][4], b[8][2];
            #pragma unroll
            for (int mi = 0; mi < 2; ++mi)
                LDSM_X4(a[mi], sA + s2 * 4096 + aAddr[mi]);
            #pragma unroll
            for (int p = 0; p < 4; ++p) {
                uint32_t t4[4];
                LDSM_X4T(t4, sA + s2 * 4096 + bAddr[p]);
                b[2*p][0] = t4[0]; b[2*p][1] = t4[1];
                b[2*p+1][0] = t4[2]; b[2*p+1][1] = t4[3];
            }
            #pragma unroll
            for (int mi = 0; mi < 2; ++mi)
                #pragma unroll
                for (int ni = 0; ni < 8; ++ni)
                    mma_f16(acc[mi][ni], a[mi], b[ni]);
        }
    }
    __syncthreads();   // stages dead; smem reused for epilogue restage

    // ---- epilogue: acc -> smem (padded) -> coalesced global stores
    const int grp = lane >> 2, qid = lane & 3;
    if (GATHER) {
        // fp16 out: buf[128 rows][272B stride], row data = 256B (128 half cols)
        constexpr int RS = 272;   // multiple of 16 -> aligned float4 reads
        #pragma unroll
        for (int mi = 0; mi < 2; ++mi) {
            const int r = wm * 32 + mi * 16 + grp;
            #pragma unroll
            for (int ni = 0; ni < 8; ++ni) {
                const int c = wn * 64 + ni * 8 + qid * 2;
                const float2 bv = *(const float2*)(bias + n0 + c);
                __half2 h0 = __floats2half2_rn(gelu_t(acc[mi][ni][0] + bv.x),
                                               gelu_t(acc[mi][ni][1] + bv.y));
                __half2 h1 = __floats2half2_rn(gelu_t(acc[mi][ni][2] + bv.x),
                                               gelu_t(acc[mi][ni][3] + bv.y));
                *(__half2*)(smem + r * RS + c * 2)       = h0;
                *(__half2*)(smem + (r + 8) * RS + c * 2) = h1;
            }
        }
        __syncthreads();
        const int row = tid >> 1, hh = tid & 1;       // 2 threads per 256B row
        const int gr = m0 + row;
        if (gr < cnt) {
            char* dst = (char*)(g_hf + ((size_t)e * TKN + gr) * NOUT + n0) + hh * 128;
            const char* src = smem + row * RS + hh * 128;
            #pragma unroll
            for (int i = 0; i < 8; ++i)
                *(float4*)(dst + i * 16) = *(const float4*)(src + i * 16);
        }
    } else {
        // fp32 out: buf[128 rows][528B stride], row data = 512B (128 float cols)
        constexpr int RS = 528;   // multiple of 16
        #pragma unroll
        for (int mi = 0; mi < 2; ++mi) {
            const int r = wm * 32 + mi * 16 + grp;
            #pragma unroll
            for (int ni = 0; ni < 8; ++ni) {
                const int c = wn * 64 + ni * 8 + qid * 2;
                const float2 bv = *(const float2*)(bias + n0 + c);
                *(float2*)(smem + r * RS + c * 4) =
                    make_float2(acc[mi][ni][0] + bv.x, acc[mi][ni][1] + bv.y);
                *(float2*)(smem + (r + 8) * RS + c * 4) =
                    make_float2(acc[mi][ni][2] + bv.x, acc[mi][ni][3] + bv.y);
            }
        }
        __syncthreads();
        const int row = tid >> 1, hh = tid & 1;       // 2 threads per 512B row
        const int gr = m0 + row;
        if (gr < cnt) {
            char* dst = (char*)(g_o2 + ((size_t)e * TKN + gr) * NOUT + n0) + hh * 256;
            const char* src = smem + row * RS + hh * 256;
            #pragma unroll
            for (int i = 0; i < 16; ++i)
                *(float4*)(dst + i * 16) = *(const float4*)(src + i * 16);
        }
    }
}

// out = x + shared + w0*routed0 + w1*routed1
__global__ void combine_kernel(const float* __restrict__ x, float* __restrict__ out) {
    int t = blockIdx.x, tid = threadIdx.x;
    int e0 = g_re[2*t],     s0 = g_rs[2*t];
    int e1 = g_re[2*t + 1], s1 = g_rs[2*t + 1];
    float w0 = g_rw[2*t], w1 = g_rw[2*t + 1];
    const float4* xp  = (const float4*)(x + (size_t)t * DIM);
    const float4* shp = (const float4*)(g_o2 + ((size_t)NEXP * TKN + t) * DIM);
    const float4* r0p = (const float4*)(g_o2 + ((size_t)e0 * TKN + s0) * DIM);
    const float4* r1p = (const float4*)(g_o2 + ((size_t)e1 * TKN + s1) * DIM);
    float4 xv = xp[tid], sv = shp[tid], a = r0p[tid], b = r1p[tid];
    float4 o;
    o.x = xv.x + sv.x + w0 * a.x + w1 * b.x;
    o.y = xv.y + sv.y + w0 * a.y + w1 * b.y;
    o.z = xv.z + sv.z + w0 * a.z + w1 * b.z;
    o.w = xv.w + sv.w + w0 * a.w + w1 * b.w;
    ((float4*)(out + (size_t)t * DIM))[tid] = o;
}

// ---------------------------------------------------------------------------
extern "C" void kernel_launch(void* const* d_in, const int* in_sizes, int n_in,
                              void* d_out, int out_size) {
    const float* x   = (const float*)d_in[0];
    const float* tc  = (const float*)d_in[1];
    const float* aw  = (const float*)d_in[2];
    const float* ab  = (const float*)d_in[3];
    const float* gw  = (const float*)d_in[4];
    const float* w1  = (const float*)d_in[5];
    const float* b1  = (const float*)d_in[6];
    const float* w2  = (const float*)d_in[7];
    const float* b2  = (const float*)d_in[8];
    const float* sw1 = (const float*)d_in[9];
    const float* sb1 = (const float*)d_in[10];
    const float* sw2 = (const float*)d_in[11];
    const float* sb2 = (const float*)d_in[12];
    float* out = (float*)d_out;

    cudaFuncSetAttribute(moe_hgemm<true >, cudaFuncAttributeMaxDynamicSharedMemorySize, SMEM_BYTES);
    cudaFuncSetAttribute(moe_hgemm<false>, cudaFuncAttributeMaxDynamicSharedMemorySize, SMEM_BYTES);

    void* p;
    cudaGetSymbolAddress(&p, g_w1h);  uint2* w1h = (uint2*)p;
    cudaGetSymbolAddress(&p, g_w2h);  uint2* w2h = (uint2*)p;
    cudaGetSymbolAddress(&p, g_sw1h); uint2* s1h = (uint2*)p;
    cudaGetSymbolAddress(&p, g_sw2h); uint2* s2h = (uint2*)p;

    init_kernel<<<1, 32>>>();                                            // #0
    cond_kernel<<<dim3((2 * DIM) / 256, NBATCH), 256>>>(tc, aw, ab);     // #1
    adaln_route<<<TKN, 256>>>(x, gw);                                    // #2
    {
        long total4 = 2L * NEXP * DIM * HID / 4 + 2L * DIM * HID / 4;
        f2h_all<<<(int)((total4 + 255) / 256), 256>>>(                   // #3
            (const float4*)w1, (const float4*)w2, (const float4*)sw1, (const float4*)sw2,
            w1h, w2h, s1h, s2h);
    }
    moe_hgemm<true ><<<dim3(HID / BN, TKN / BM, 9), 256, SMEM_BYTES>>>(  // #4
        (const __half*)w1h, (const __half*)s1h, b1, sb1);
    moe_hgemm<false><<<dim3(DIM / BN, TKN / BM, 9), 256, SMEM_BYTES>>>(  // #5
        (const __half*)w2h, (const __half*)s2h, b2, sb2);
    combine_kernel<<<TKN, 256>>>(x, out);                                // #6
}

// round 14
// speedup vs baseline: 1.1007x; 1.1007x over previous
#include <cuda_runtime.h>
#include <cuda_fp16.h>
#include <cstdint>
#include <cstddef>

// ---------------------------------------------------------------------------
// GlobalFeatureMoE: AdaLN + top-2 MoE (8 routed + 1 shared expert) + residual
// fp16 mma.sync.m16n8k16 (fp32 accum), 128x128xBK32 tiles, 4-stage cp.async,
// 2 CTAs/SM (R6 mainloop) + coalesced smem-restaged epilogues.
// ---------------------------------------------------------------------------

constexpr int TKN  = 8192;   // B*L
constexpr int DIM  = 1024;
constexpr int NEXP = 8;
constexpr int HID  = 4096;
constexpr int NBATCH = 4;
constexpr int SEQ  = 2048;

constexpr int BM = 128, BN = 128, BK = 32, NSTAGE = 4;
constexpr int STAGE = 16384;               // A 8KB (2 x 4KB k16-halves) + B 8KB
constexpr int SMEM_BYTES = 67584;          // stages 65536; fp32 restage 128*528

// scratch (static __device__ arrays — allocation-free per harness rules)
__device__ float  g_cond[NBATCH * 2 * DIM];
__device__ int    g_cnt[NEXP];
__device__ int    g_idx[NEXP * TKN];
__device__ int    g_re[2 * TKN];
__device__ int    g_rs[2 * TKN];
__device__ float  g_rw[2 * TKN];
__device__ __half g_xnh[(size_t)TKN * DIM];          // fp16 normalized tokens
__device__ __half g_hf [(size_t)9 * TKN * HID];      // fp16 hidden per bucket
__device__ float  g_o2 [(size_t)9 * TKN * DIM];      // fp32 expert outputs
__device__ __half g_w1h[(size_t)NEXP * DIM * HID];
__device__ __half g_w2h[(size_t)NEXP * HID * DIM];
__device__ __half g_sw1h[(size_t)DIM * HID];
__device__ __half g_sw2h[(size_t)HID * DIM];

// ---------------------------------------------------------------------------
__device__ __forceinline__ uint32_t smem_u32(const void* p) {
    uint32_t a;
    asm("{ .reg .u64 t; cvta.to.shared.u64 t, %1; cvt.u32.u64 %0, t; }" : "=r"(a) : "l"(p));
    return a;
}
#define CP_ASYNC16(dst, src) \
    asm volatile("cp.async.cg.shared.global [%0], [%1], 16;" :: "r"(dst), "l"(src))
#define CP_COMMIT() asm volatile("cp.async.commit_group;" ::: "memory")
#define CP_WAIT(n)  asm volatile("cp.async.wait_group %0;" :: "n"(n) : "memory")

#define LDSM_X4(r, addr) \
    asm volatile("ldmatrix.sync.aligned.m8n8.x4.shared.b16 {%0,%1,%2,%3}, [%4];" \
        : "=r"((r)[0]), "=r"((r)[1]), "=r"((r)[2]), "=r"((r)[3]) : "r"(addr))
#define LDSM_X4T(r, addr) \
    asm volatile("ldmatrix.sync.aligned.m8n8.x4.trans.shared.b16 {%0,%1,%2,%3}, [%4];" \
        : "=r"((r)[0]), "=r"((r)[1]), "=r"((r)[2]), "=r"((r)[3]) : "r"(addr))

__device__ __forceinline__ void mma_f16(float* c, const uint32_t* a, const uint32_t* b) {
    asm volatile(
        "mma.sync.aligned.m16n8k16.row.col.f32.f16.f16.f32 "
        "{%0,%1,%2,%3}, {%4,%5,%6,%7}, {%8,%9}, {%0,%1,%2,%3};\n"
        : "+f"(c[0]), "+f"(c[1]), "+f"(c[2]), "+f"(c[3])
        : "r"(a[0]), "r"(a[1]), "r"(a[2]), "r"(a[3]), "r"(b[0]), "r"(b[1]));
}

__device__ __forceinline__ float gelu_t(float v) {
    float u = 0.7978845608028654f * (v + 0.044715f * v * v * v);
    return 0.5f * v * (1.0f + tanhf(u));
}

// ---------------------------------------------------------------------------
// single-launch fp32 -> fp16 conversion of all four weight matrices
__global__ void f2h_all(const float4* __restrict__ w1, const float4* __restrict__ w2,
                        const float4* __restrict__ s1, const float4* __restrict__ s2,
                        uint2* __restrict__ o1, uint2* __restrict__ o2,
                        uint2* __restrict__ o3, uint2* __restrict__ o4) {
    constexpr long N1 = (long)NEXP * DIM * HID / 4;   // 8388608
    constexpr long NS = (long)DIM * HID / 4;          // 1048576
    long i = (long)blockIdx.x * blockDim.x + threadIdx.x;
    const float4* in; uint2* out; long j;
    if      (i < N1)           { in = w1; out = o1; j = i; }
    else if (i < 2 * N1)       { in = w2; out = o2; j = i - N1; }
    else if (i < 2 * N1 + NS)  { in = s1; out = o3; j = i - 2 * N1; }
    else if (i < 2 * N1 + 2*NS){ in = s2; out = o4; j = i - 2 * N1 - NS; }
    else return;
    float4 v = in[j];
    __half2 a = __floats2half2_rn(v.x, v.y);
    __half2 b = __floats2half2_rn(v.z, v.w);
    out[j] = make_uint2(*(uint32_t*)&a, *(uint32_t*)&b);
}

// cond = silu(time_c) @ ada_w + ada_b   (also zeroes routing counters)
__global__ void cond_kernel(const float* __restrict__ tc,
                            const float* __restrict__ aw,
                            const float* __restrict__ ab) {
    if (blockIdx.x == 0 && blockIdx.y == 0 && threadIdx.x < NEXP)
        g_cnt[threadIdx.x] = 0;
    __shared__ float s[DIM];
    int b = blockIdx.y;
    for (int i = threadIdx.x; i < DIM; i += blockDim.x) {
        float v = tc[(size_t)b * DIM + i];
        s[i] = v / (1.0f + expf(-v));
    }
    __syncthreads();
    int col = blockIdx.x * blockDim.x + threadIdx.x;
    float acc = ab[col];
    #pragma unroll 8
    for (int k = 0; k < DIM; ++k)
        acc += s[k] * aw[(size_t)k * (2 * DIM) + col];
    g_cond[(size_t)b * (2 * DIM) + col] = acc;
}

// fused AdaLN + fp32 gate + top-2 routing; writes fp16 xn
__global__ void adaln_route(const float* __restrict__ x,
                            const float* __restrict__ gw) {
    int t   = blockIdx.x;
    int tid = threadIdx.x;
    int lane = tid & 31, wid = tid >> 5;
    int b = t / SEQ;

    float4 xv = reinterpret_cast<const float4*>(x + (size_t)t * DIM)[tid];
    float s  = xv.x + xv.y + xv.z + xv.w;
    float ss = xv.x*xv.x + xv.y*xv.y + xv.z*xv.z + xv.w*xv.w;
    #pragma unroll
    for (int o = 16; o > 0; o >>= 1) {
        s  += __shfl_down_sync(0xffffffffu, s,  o);
        ss += __shfl_down_sync(0xffffffffu, ss, o);
    }
    __shared__ float red[2][8];
    if (lane == 0) { red[0][wid] = s; red[1][wid] = ss; }
    __syncthreads();
    float mu = 0.f, m2 = 0.f;
    #pragma unroll
    for (int w = 0; w < 8; ++w) { mu += red[0][w]; m2 += red[1][w]; }
    mu *= (1.0f / DIM); m2 *= (1.0f / DIM);
    float rstd = rsqrtf(m2 - mu * mu + 1e-6f);

    float4 sh = reinterpret_cast<const float4*>(g_cond + (size_t)b*2*DIM)[tid];
    float4 sc = reinterpret_cast<const float4*>(g_cond + (size_t)b*2*DIM + DIM)[tid];
    float4 xn;
    xn.x = (xv.x - mu) * rstd * (1.0f + sc.x) + sh.x;
    xn.y = (xv.y - mu) * rstd * (1.0f + sc.y) + sh.y;
    xn.z = (xv.z - mu) * rstd * (1.0f + sc.z) + sh.z;
    xn.w = (xv.w - mu) * rstd * (1.0f + sc.w) + sh.w;
    {
        __half2 h01 = __floats2half2_rn(xn.x, xn.y);
        __half2 h23 = __floats2half2_rn(xn.z, xn.w);
        *(uint2*)(g_xnh + (size_t)t * DIM + tid * 4) =
            make_uint2(*(uint32_t*)&h01, *(uint32_t*)&h23);
    }

    // gate logits in exact fp32
    float l[8];
    #pragma unroll
    for (int e = 0; e < 8; ++e) l[e] = 0.f;
    int d = tid * 4;
    float xs[4] = {xn.x, xn.y, xn.z, xn.w};
    #pragma unroll
    for (int j = 0; j < 4; ++j) {
        const float* wr = gw + (size_t)(d + j) * NEXP;
        #pragma unroll
        for (int e = 0; e < 8; ++e) l[e] += xs[j] * wr[e];
    }
    #pragma unroll
    for (int e = 0; e < 8; ++e) {
        #pragma unroll
        for (int o = 16; o > 0; o >>= 1)
            l[e] += __shfl_down_sync(0xffffffffu, l[e], o);
    }
    __shared__ float lred[8][8];
    if (lane == 0) {
        #pragma unroll
        for (int e = 0; e < 8; ++e) lred[e][wid] = l[e];
    }
    __syncthreads();
    if (tid == 0) {
        float L[8];
        #pragma unroll
        for (int e = 0; e < 8; ++e) {
            float a = 0.f;
            for (int w = 0; w < 8; ++w) a += lred[e][w];
            L[e] = a;
        }
        float mx = L[0];
        for (int e = 1; e < 8; ++e) mx = fmaxf(mx, L[e]);
        float p[8];
        for (int e = 0; e < 8; ++e) p[e] = expf(L[e] - mx);
        int ia = 0; float va = p[0];
        for (int e = 1; e < 8; ++e) if (p[e] > va) { ia = e; va = p[e]; }
        int ib = -1; float vb = -1.f;
        for (int e = 0; e < 8; ++e) if (e != ia && p[e] > vb) { ib = e; vb = p[e]; }
        float inv = 1.0f / (va + vb);
        int sa = atomicAdd(&g_cnt[ia], 1);
        int sb = atomicAdd(&g_cnt[ib], 1);
        g_idx[ia * TKN + sa] = t;
        g_idx[ib * TKN + sb] = t;
        g_re[2*t]   = ia; g_rs[2*t]   = sa; g_rw[2*t]   = va * inv;
        g_re[2*t+1] = ib; g_rs[2*t+1] = sb; g_rw[2*t+1] = vb * inv;
    }
}

// ---------------------------------------------------------------------------
// fp16 GEMM: CTA 128x128xBK32, 8 warps (4m x 2n) of 32x64, 4-stage cp.async,
// 2 CTAs/SM.  blockIdx.z = expert (0..7 routed, 8 = shared)
// A smem (per stage): 2 k16-halves of [128 rows][32B]; granule c of row r at
//   half*4096 + r*32 + ((c ^ ((r>>2)&1))<<4)
// B smem (per stage, base 8192): [32 k][256B]; granule g of row k at
//   k*256 + ((g ^ (k&7))<<4)
// ---------------------------------------------------------------------------
template <bool GATHER>   // true: xnh -> gelu(xW1+b1) = g_hf ; false: g_hf -> hW2+b2 = g_o2
__global__ __launch_bounds__(256, 2) void moe_hgemm(
    const __half* __restrict__ Wr, const __half* __restrict__ Ws,
    const float* __restrict__ br, const float* __restrict__ bs) {
    constexpr int NOUT = GATHER ? HID : DIM;
    constexpr int KD   = GATHER ? DIM : HID;
    constexpr int NKT  = KD / BK;

    extern __shared__ char smem[];
    const int e   = blockIdx.z;
    const int cnt = (e < NEXP) ? g_cnt[e] : TKN;
    const int m0  = blockIdx.y * BM;
    if (m0 >= cnt) return;
    const int n0  = blockIdx.x * BN;
    const __half* W    = (e < NEXP) ? Wr + (size_t)e * KD * NOUT : Ws;
    const float*  bias = (e < NEXP) ? br + (size_t)e * NOUT      : bs;
    const __half* Ah   = GATHER ? g_xnh : g_hf;

    const uint32_t sbase = smem_u32(smem);
    const int tid = threadIdx.x, lane = tid & 31, wid = tid >> 5;
    const int wm = wid >> 1, wn = wid & 1;

    // ---- staging: A row tid&127 (half tid>>7, 2 granules), B 2 granules
    const int arow = tid & 127, ahalf = tid >> 7;
    int gr_s = m0 + arow;
    long aidx;
    if (GATHER) aidx = (e < NEXP) ? ((gr_s < cnt) ? g_idx[e * TKN + gr_s] : 0) : gr_s;
    else        aidx = (long)e * TKN + gr_s;
    const char* aRow = (const char*)(Ah + (size_t)aidx * KD) + ahalf * 32;
    uint32_t aOff[2];
    #pragma unroll
    for (int c = 0; c < 2; ++c)
        aOff[c] = (uint32_t)(ahalf * 4096 + arow * 32 + ((c ^ ((arow >> 2) & 1)) << 4));
    const int bk0 = tid >> 3;                 // 0..31
    const int gn0 = (tid & 7) * 2;            // even granule 0..14
    const char* bRow = (const char*)(W + (size_t)bk0 * NOUT + n0 + gn0 * 8);
    uint32_t bOff[2];
    #pragma unroll
    for (int c = 0; c < 2; ++c)
        bOff[c] = (uint32_t)(8192 + bk0 * 256 + (((gn0 + c) ^ (bk0 & 7)) << 4));
    const size_t bStride = (size_t)BK * NOUT * sizeof(__half);

    auto load_stage = [&](int kt) {
        uint32_t so = sbase + (uint32_t)((kt & (NSTAGE - 1)) * STAGE);
        const char* as = aRow + (size_t)kt * (BK * 2);
        CP_ASYNC16(so + aOff[0], as);
        CP_ASYNC16(so + aOff[1], as + 16);
        const char* bsrc = bRow + (size_t)kt * bStride;
        CP_ASYNC16(so + bOff[0], bsrc);
        CP_ASYNC16(so + bOff[1], bsrc + 16);
        CP_COMMIT();
    };

    // ---- fragment addresses (stage-relative)
    const int rr = lane & 15, cc = lane >> 4;
    const uint32_t aswz = (uint32_t)((cc ^ ((rr >> 2) & 1)) << 4);
    uint32_t aAddr[2];
    #pragma unroll
    for (int mi = 0; mi < 2; ++mi)
        aAddr[mi] = (uint32_t)((wm * 32 + mi * 16 + rr) * 32) + aswz;
    const int kk = ((lane >> 3) & 1) * 8 + (lane & 7);
    const int j2 = lane >> 4;
    uint32_t bAddr[4];
    #pragma unroll
    for (int p = 0; p < 4; ++p)
        bAddr[p] = (uint32_t)(8192 + kk * 256 + (((wn * 8 + p * 2 + j2) ^ (lane & 7)) << 4));

    float acc[2][8][4];
    #pragma unroll
    for (int mi = 0; mi < 2; ++mi)
        #pragma unroll
        for (int ni = 0; ni < 8; ++ni)
            #pragma unroll
            for (int q = 0; q < 4; ++q) acc[mi][ni][q] = 0.f;

    load_stage(0); load_stage(1); load_stage(2);

    for (int kt = 0; kt < NKT; ++kt) {
        CP_WAIT(2);
        __syncthreads();
        if (kt + 3 < NKT) load_stage(kt + 3); else CP_COMMIT();

        const uint32_t sA = sbase + (uint32_t)((kt & (NSTAGE - 1)) * STAGE);
        #pragma unroll
        for (int s2 = 0; s2 < 2; ++s2) {
            uint32_t a[2][4], b[8][2];
            #pragma unroll
            for (int mi = 0; mi < 2; ++mi)
                LDSM_X4(a[mi], sA + s2 * 4096 + aAddr[mi]);
            #pragma unroll
            for (int p = 0; p < 4; ++p) {
                uint32_t t4[4];
                LDSM_X4T(t4, sA + s2 * 4096 + bAddr[p]);
                b[2*p][0] = t4[0]; b[2*p][1] = t4[1];
                b[2*p+1][0] = t4[2]; b[2*p+1][1] = t4[3];
            }
            #pragma unroll
            for (int mi = 0; mi < 2; ++mi)
                #pragma unroll
                for (int ni = 0; ni < 8; ++ni)
                    mma_f16(acc[mi][ni], a[mi], b[ni]);
        }
    }
    __syncthreads();   // stages dead; smem reused for epilogue restage

    // ---- epilogue: acc -> smem (padded) -> coalesced global stores
    const int grp = lane >> 2, qid = lane & 3;
    if (GATHER) {
        // fp16 out: buf[128 rows][272B stride], row data = 256B (128 half cols)
        constexpr int RS = 272;   // multiple of 16 -> aligned float4 reads
        #pragma unroll
        for (int mi = 0; mi < 2; ++mi) {
            const int r = wm * 32 + mi * 16 + grp;
            #pragma unroll
            for (int ni = 0; ni < 8; ++ni) {
                const int c = wn * 64 + ni * 8 + qid * 2;
                const float2 bv = *(const float2*)(bias + n0 + c);
                __half2 h0 = __floats2half2_rn(gelu_t(acc[mi][ni][0] + bv.x),
                                               gelu_t(acc[mi][ni][1] + bv.y));
                __half2 h1 = __floats2half2_rn(gelu_t(acc[mi][ni][2] + bv.x),
                                               gelu_t(acc[mi][ni][3] + bv.y));
                *(__half2*)(smem + r * RS + c * 2)       = h0;
                *(__half2*)(smem + (r + 8) * RS + c * 2) = h1;
            }
        }
        __syncthreads();
        const int row = tid >> 1, hh = tid & 1;       // 2 threads per 256B row
        const int gr = m0 + row;
        if (gr < cnt) {
            char* dst = (char*)(g_hf + ((size_t)e * TKN + gr) * NOUT + n0) + hh * 128;
            const char* src = smem + row * RS + hh * 128;
            #pragma unroll
            for (int i = 0; i < 8; ++i)
                *(float4*)(dst + i * 16) = *(const float4*)(src + i * 16);
        }
    } else {
        // fp32 out: buf[128 rows][528B stride], row data = 512B (128 float cols)
        constexpr int RS = 528;   // multiple of 16
        #pragma unroll
        for (int mi = 0; mi < 2; ++mi) {
            const int r = wm * 32 + mi * 16 + grp;
            #pragma unroll
            for (int ni = 0; ni < 8; ++ni) {
                const int c = wn * 64 + ni * 8 + qid * 2;
                const float2 bv = *(const float2*)(bias + n0 + c);
                *(float2*)(smem + r * RS + c * 4) =
                    make_float2(acc[mi][ni][0] + bv.x, acc[mi][ni][1] + bv.y);
                *(float2*)(smem + (r + 8) * RS + c * 4) =
                    make_float2(acc[mi][ni][2] + bv.x, acc[mi][ni][3] + bv.y);
            }
        }
        __syncthreads();
        const int row = tid >> 1, hh = tid & 1;       // 2 threads per 512B row
        const int gr = m0 + row;
        if (gr < cnt) {
            char* dst = (char*)(g_o2 + ((size_t)e * TKN + gr) * NOUT + n0) + hh * 256;
            const char* src = smem + row * RS + hh * 256;
            #pragma unroll
            for (int i = 0; i < 16; ++i)
                *(float4*)(dst + i * 16) = *(const float4*)(src + i * 16);
        }
    }
}

// out = x + shared + w0*routed0 + w1*routed1
__global__ void combine_kernel(const float* __restrict__ x, float* __restrict__ out) {
    int t = blockIdx.x, tid = threadIdx.x;
    int e0 = g_re[2*t],     s0 = g_rs[2*t];
    int e1 = g_re[2*t + 1], s1 = g_rs[2*t + 1];
    float w0 = g_rw[2*t], w1 = g_rw[2*t + 1];
    const float4* xp  = (const float4*)(x + (size_t)t * DIM);
    const float4* shp = (const float4*)(g_o2 + ((size_t)NEXP * TKN + t) * DIM);
    const float4* r0p = (const float4*)(g_o2 + ((size_t)e0 * TKN + s0) * DIM);
    const float4* r1p = (const float4*)(g_o2 + ((size_t)e1 * TKN + s1) * DIM);
    float4 xv = xp[tid], sv = shp[tid], a = r0p[tid], b = r1p[tid];
    float4 o;
    o.x = xv.x + sv.x + w0 * a.x + w1 * b.x;
    o.y = xv.y + sv.y + w0 * a.y + w1 * b.y;
    o.z = xv.z + sv.z + w0 * a.z + w1 * b.z;
    o.w = xv.w + sv.w + w0 * a.w + w1 * b.w;
    ((float4*)(out + (size_t)t * DIM))[tid] = o;
}

// ---------------------------------------------------------------------------
extern "C" void kernel_launch(void* const* d_in, const int* in_sizes, int n_in,
                              void* d_out, int out_size) {
    const float* x   = (const float*)d_in[0];
    const float* tc  = (const float*)d_in[1];
    const float* aw  = (const float*)d_in[2];
    const float* ab  = (const float*)d_in[3];
    const float* gw  = (const float*)d_in[4];
    const float* w1  = (const float*)d_in[5];
    const float* b1  = (const float*)d_in[6];
    const float* w2  = (const float*)d_in[7];
    const float* b2  = (const float*)d_in[8];
    const float* sw1 = (const float*)d_in[9];
    const float* sb1 = (const float*)d_in[10];
    const float* sw2 = (const float*)d_in[11];
    const float* sb2 = (const float*)d_in[12];
    float* out = (float*)d_out;

    cudaFuncSetAttribute(moe_hgemm<true >, cudaFuncAttributeMaxDynamicSharedMemorySize, SMEM_BYTES);
    cudaFuncSetAttribute(moe_hgemm<false>, cudaFuncAttributeMaxDynamicSharedMemorySize, SMEM_BYTES);

    void* p;
    cudaGetSymbolAddress(&p, g_w1h);  uint2* w1h = (uint2*)p;
    cudaGetSymbolAddress(&p, g_w2h);  uint2* w2h = (uint2*)p;
    cudaGetSymbolAddress(&p, g_sw1h); uint2* s1h = (uint2*)p;
    cudaGetSymbolAddress(&p, g_sw2h); uint2* s2h = (uint2*)p;

    cond_kernel<<<dim3((2 * DIM) / 256, NBATCH), 256>>>(tc, aw, ab);     // user #0 (+init)
    adaln_route<<<TKN, 256>>>(x, gw);                                    // user #1
    {
        long total4 = 2L * NEXP * DIM * HID / 4 + 2L * DIM * HID / 4;
        f2h_all<<<(int)((total4 + 255) / 256), 256>>>(                   // user #2
            (const float4*)w1, (const float4*)w2, (const float4*)sw1, (const float4*)sw2,
            w1h, w2h, s1h, s2h);
    }
    moe_hgemm<true ><<<dim3(HID / BN, TKN / BM, 9), 256, SMEM_BYTES>>>(  // user #3 (profiled)
        (const __half*)w1h, (const __half*)s1h, b1, sb1);
    moe_hgemm<false><<<dim3(DIM / BN, TKN / BM, 9), 256, SMEM_BYTES>>>(  // user #4
        (const __half*)w2h, (const __half*)s2h, b2, sb2);
    combine_kernel<<<TKN, 256>>>(x, out);                                // user #5
}

// round 16
// speedup vs baseline: 1.1043x; 1.0033x over previous
#include <cuda_runtime.h>
#include <cuda_fp16.h>
#include <cstdint>
#include <cstddef>

// ---------------------------------------------------------------------------
// GlobalFeatureMoE: AdaLN + top-2 MoE (8 routed + 1 shared expert) + residual
// fp16 mma.sync.m16n8k16 (fp32 accum), 128x128xBK32 CTA tiles, 4-stage
// cp.async, 128-thread CTAs (4 warps of 64x64, high-ILP), 2 CTAs/SM,
// direct epilogue stores (restage reverted — it regressed R14).
// ---------------------------------------------------------------------------

constexpr int TKN  = 8192;   // B*L
constexpr int DIM  = 1024;
constexpr int NEXP = 8;
constexpr int HID  = 4096;
constexpr int NBATCH = 4;
constexpr int SEQ  = 2048;

constexpr int BM = 128, BN = 128, BK = 32, NSTAGE = 4;
constexpr int STAGE = 16384;               // A 8KB (2 x 4KB k16-halves) + B 8KB
constexpr int SMEM_BYTES = NSTAGE * STAGE; // 65536 -> 2 CTAs/SM

// scratch (static __device__ arrays — allocation-free per harness rules)
__device__ float  g_cond[NBATCH * 2 * DIM];
__device__ int    g_cnt[NEXP];
__device__ int    g_idx[NEXP * TKN];
__device__ int    g_re[2 * TKN];
__device__ int    g_rs[2 * TKN];
__device__ float  g_rw[2 * TKN];
__device__ __half g_xnh[(size_t)TKN * DIM];          // fp16 normalized tokens
__device__ __half g_hf [(size_t)9 * TKN * HID];      // fp16 hidden per bucket
__device__ float  g_o2 [(size_t)9 * TKN * DIM];      // fp32 expert outputs
__device__ __half g_w1h[(size_t)NEXP * DIM * HID];
__device__ __half g_w2h[(size_t)NEXP * HID * DIM];
__device__ __half g_sw1h[(size_t)DIM * HID];
__device__ __half g_sw2h[(size_t)HID * DIM];

// ---------------------------------------------------------------------------
__device__ __forceinline__ uint32_t smem_u32(const void* p) {
    uint32_t a;
    asm("{ .reg .u64 t; cvta.to.shared.u64 t, %1; cvt.u32.u64 %0, t; }" : "=r"(a) : "l"(p));
    return a;
}
#define CP_ASYNC16(dst, src) \
    asm volatile("cp.async.cg.shared.global [%0], [%1], 16;" :: "r"(dst), "l"(src))
#define CP_COMMIT() asm volatile("cp.async.commit_group;" ::: "memory")
#define CP_WAIT(n)  asm volatile("cp.async.wait_group %0;" :: "n"(n) : "memory")

#define LDSM_X4(r, addr) \
    asm volatile("ldmatrix.sync.aligned.m8n8.x4.shared.b16 {%0,%1,%2,%3}, [%4];" \
        : "=r"((r)[0]), "=r"((r)[1]), "=r"((r)[2]), "=r"((r)[3]) : "r"(addr))
#define LDSM_X4T(r, addr) \
    asm volatile("ldmatrix.sync.aligned.m8n8.x4.trans.shared.b16 {%0,%1,%2,%3}, [%4];" \
        : "=r"((r)[0]), "=r"((r)[1]), "=r"((r)[2]), "=r"((r)[3]) : "r"(addr))

__device__ __forceinline__ void mma_f16(float* c, const uint32_t* a, const uint32_t* b) {
    asm volatile(
        "mma.sync.aligned.m16n8k16.row.col.f32.f16.f16.f32 "
        "{%0,%1,%2,%3}, {%4,%5,%6,%7}, {%8,%9}, {%0,%1,%2,%3};\n"
        : "+f"(c[0]), "+f"(c[1]), "+f"(c[2]), "+f"(c[3])
        : "r"(a[0]), "r"(a[1]), "r"(a[2]), "r"(a[3]), "r"(b[0]), "r"(b[1]));
}

__device__ __forceinline__ float gelu_t(float v) {
    float u = 0.7978845608028654f * (v + 0.044715f * v * v * v);
    return 0.5f * v * (1.0f + tanhf(u));
}

// ---------------------------------------------------------------------------
// single-launch fp32 -> fp16 conversion of all four weight matrices
__global__ void f2h_all(const float4* __restrict__ w1, const float4* __restrict__ w2,
                        const float4* __restrict__ s1, const float4* __restrict__ s2,
                        uint2* __restrict__ o1, uint2* __restrict__ o2,
                        uint2* __restrict__ o3, uint2* __restrict__ o4) {
    constexpr long N1 = (long)NEXP * DIM * HID / 4;   // 8388608
    constexpr long NS = (long)DIM * HID / 4;          // 1048576
    long i = (long)blockIdx.x * blockDim.x + threadIdx.x;
    const float4* in; uint2* out; long j;
    if      (i < N1)           { in = w1; out = o1; j = i; }
    else if (i < 2 * N1)       { in = w2; out = o2; j = i - N1; }
    else if (i < 2 * N1 + NS)  { in = s1; out = o3; j = i - 2 * N1; }
    else if (i < 2 * N1 + 2*NS){ in = s2; out = o4; j = i - 2 * N1 - NS; }
    else return;
    float4 v = in[j];
    __half2 a = __floats2half2_rn(v.x, v.y);
    __half2 b = __floats2half2_rn(v.z, v.w);
    out[j] = make_uint2(*(uint32_t*)&a, *(uint32_t*)&b);
}

// cond = silu(time_c) @ ada_w + ada_b   (also zeroes routing counters)
__global__ void cond_kernel(const float* __restrict__ tc,
                            const float* __restrict__ aw,
                            const float* __restrict__ ab) {
    if (blockIdx.x == 0 && blockIdx.y == 0 && threadIdx.x < NEXP)
        g_cnt[threadIdx.x] = 0;
    __shared__ float s[DIM];
    int b = blockIdx.y;
    for (int i = threadIdx.x; i < DIM; i += blockDim.x) {
        float v = tc[(size_t)b * DIM + i];
        s[i] = v / (1.0f + expf(-v));
    }
    __syncthreads();
    int col = blockIdx.x * blockDim.x + threadIdx.x;
    float acc = ab[col];
    #pragma unroll 8
    for (int k = 0; k < DIM; ++k)
        acc += s[k] * aw[(size_t)k * (2 * DIM) + col];
    g_cond[(size_t)b * (2 * DIM) + col] = acc;
}

// fused AdaLN + fp32 gate + top-2 routing; writes fp16 xn
__global__ void adaln_route(const float* __restrict__ x,
                            const float* __restrict__ gw) {
    int t   = blockIdx.x;
    int tid = threadIdx.x;
    int lane = tid & 31, wid = tid >> 5;
    int b = t / SEQ;

    float4 xv = reinterpret_cast<const float4*>(x + (size_t)t * DIM)[tid];
    float s  = xv.x + xv.y + xv.z + xv.w;
    float ss = xv.x*xv.x + xv.y*xv.y + xv.z*xv.z + xv.w*xv.w;
    #pragma unroll
    for (int o = 16; o > 0; o >>= 1) {
        s  += __shfl_down_sync(0xffffffffu, s,  o);
        ss += __shfl_down_sync(0xffffffffu, ss, o);
    }
    __shared__ float red[2][8];
    if (lane == 0) { red[0][wid] = s; red[1][wid] = ss; }
    __syncthreads();
    float mu = 0.f, m2 = 0.f;
    #pragma unroll
    for (int w = 0; w < 8; ++w) { mu += red[0][w]; m2 += red[1][w]; }
    mu *= (1.0f / DIM); m2 *= (1.0f / DIM);
    float rstd = rsqrtf(m2 - mu * mu + 1e-6f);

    float4 sh = reinterpret_cast<const float4*>(g_cond + (size_t)b*2*DIM)[tid];
    float4 sc = reinterpret_cast<const float4*>(g_cond + (size_t)b*2*DIM + DIM)[tid];
    float4 xn;
    xn.x = (xv.x - mu) * rstd * (1.0f + sc.x) + sh.x;
    xn.y = (xv.y - mu) * rstd * (1.0f + sc.y) + sh.y;
    xn.z = (xv.z - mu) * rstd * (1.0f + sc.z) + sh.z;
    xn.w = (xv.w - mu) * rstd * (1.0f + sc.w) + sh.w;
    {
        __half2 h01 = __floats2half2_rn(xn.x, xn.y);
        __half2 h23 = __floats2half2_rn(xn.z, xn.w);
        *(uint2*)(g_xnh + (size_t)t * DIM + tid * 4) =
            make_uint2(*(uint32_t*)&h01, *(uint32_t*)&h23);
    }

    // gate logits in exact fp32
    float l[8];
    #pragma unroll
    for (int e = 0; e < 8; ++e) l[e] = 0.f;
    int d = tid * 4;
    float xs[4] = {xn.x, xn.y, xn.z, xn.w};
    #pragma unroll
    for (int j = 0; j < 4; ++j) {
        const float* wr = gw + (size_t)(d + j) * NEXP;
        #pragma unroll
        for (int e = 0; e < 8; ++e) l[e] += xs[j] * wr[e];
    }
    #pragma unroll
    for (int e = 0; e < 8; ++e) {
        #pragma unroll
        for (int o = 16; o > 0; o >>= 1)
            l[e] += __shfl_down_sync(0xffffffffu, l[e], o);
    }
    __shared__ float lred[8][8];
    if (lane == 0) {
        #pragma unroll
        for (int e = 0; e < 8; ++e) lred[e][wid] = l[e];
    }
    __syncthreads();
    if (tid == 0) {
        float L[8];
        #pragma unroll
        for (int e = 0; e < 8; ++e) {
            float a = 0.f;
            for (int w = 0; w < 8; ++w) a += lred[e][w];
            L[e] = a;
        }
        float mx = L[0];
        for (int e = 1; e < 8; ++e) mx = fmaxf(mx, L[e]);
        float p[8];
        for (int e = 0; e < 8; ++e) p[e] = expf(L[e] - mx);
        int ia = 0; float va = p[0];
        for (int e = 1; e < 8; ++e) if (p[e] > va) { ia = e; va = p[e]; }
        int ib = -1; float vb = -1.f;
        for (int e = 0; e < 8; ++e) if (e != ia && p[e] > vb) { ib = e; vb = p[e]; }
        float inv = 1.0f / (va + vb);
        int sa = atomicAdd(&g_cnt[ia], 1);
        int sb = atomicAdd(&g_cnt[ib], 1);
        g_idx[ia * TKN + sa] = t;
        g_idx[ib * TKN + sb] = t;
        g_re[2*t]   = ia; g_rs[2*t]   = sa; g_rw[2*t]   = va * inv;
        g_re[2*t+1] = ib; g_rs[2*t+1] = sb; g_rw[2*t+1] = vb * inv;
    }
}

// ---------------------------------------------------------------------------
// fp16 GEMM: CTA 128x128xBK32, 128 threads = 4 warps (2m x 2n) of 64x64,
// 4-stage cp.async, 2 CTAs/SM (reg ceiling 255 via launch_bounds(128,2)).
// blockIdx.z = expert (0..7 routed, 8 = shared)
// A smem (per stage): 2 k16-halves of [128 rows][32B]; granule c of row r at
//   half*4096 + r*32 + ((c ^ ((r>>2)&1))<<4)
// B smem (per stage, base 8192): [32 k][256B]; granule g of row k at
//   k*256 + ((g ^ (k&7))<<4)
// ---------------------------------------------------------------------------
template <bool GATHER>   // true: xnh -> gelu(xW1+b1) = g_hf ; false: g_hf -> hW2+b2 = g_o2
__global__ __launch_bounds__(128, 2) void moe_hgemm(
    const __half* __restrict__ Wr, const __half* __restrict__ Ws,
    const float* __restrict__ br, const float* __restrict__ bs) {
    constexpr int NOUT = GATHER ? HID : DIM;
    constexpr int KD   = GATHER ? DIM : HID;
    constexpr int NKT  = KD / BK;

    extern __shared__ char smem[];
    const int e   = blockIdx.z;
    const int cnt = (e < NEXP) ? g_cnt[e] : TKN;
    const int m0  = blockIdx.y * BM;
    if (m0 >= cnt) return;
    const int n0  = blockIdx.x * BN;
    const __half* W    = (e < NEXP) ? Wr + (size_t)e * KD * NOUT : Ws;
    const float*  bias = (e < NEXP) ? br + (size_t)e * NOUT      : bs;
    const __half* Ah   = GATHER ? g_xnh : g_hf;

    const uint32_t sbase = smem_u32(smem);
    const int tid = threadIdx.x, lane = tid & 31, wid = tid >> 5;
    const int wm = wid >> 1, wn = wid & 1;

    // ---- staging: A row tid (4 granules: 2 halves x 2), B 4 granules
    int gr_s = m0 + tid;
    long aidx;
    if (GATHER) aidx = (e < NEXP) ? ((gr_s < cnt) ? g_idx[e * TKN + gr_s] : 0) : gr_s;
    else        aidx = (long)e * TKN + gr_s;
    const char* aRow = (const char*)(Ah + (size_t)aidx * KD);
    uint32_t aOff[4];
    #pragma unroll
    for (int q = 0; q < 4; ++q) {
        int h = q >> 1, c = q & 1;
        aOff[q] = (uint32_t)(h * 4096 + tid * 32 + ((c ^ ((tid >> 2) & 1)) << 4));
    }
    const int bk0 = tid >> 2;                 // 0..31
    const int gn0 = (tid & 3) * 4;            // granule 0,4,8,12
    const char* bRow = (const char*)(W + (size_t)bk0 * NOUT + n0 + gn0 * 8);
    uint32_t bOff[4];
    #pragma unroll
    for (int c = 0; c < 4; ++c)
        bOff[c] = (uint32_t)(8192 + bk0 * 256 + (((gn0 + c) ^ (bk0 & 7)) << 4));
    const size_t bStride = (size_t)BK * NOUT * sizeof(__half);

    auto load_stage = [&](int kt) {
        uint32_t so = sbase + (uint32_t)((kt & (NSTAGE - 1)) * STAGE);
        const char* as = aRow + (size_t)kt * (BK * 2);
        CP_ASYNC16(so + aOff[0], as);          // h0 c0  (src +0)
        CP_ASYNC16(so + aOff[1], as + 16);     // h0 c1
        CP_ASYNC16(so + aOff[2], as + 32);     // h1 c0
        CP_ASYNC16(so + aOff[3], as + 48);     // h1 c1
        const char* bsrc = bRow + (size_t)kt * bStride;
        CP_ASYNC16(so + bOff[0], bsrc);
        CP_ASYNC16(so + bOff[1], bsrc + 16);
        CP_ASYNC16(so + bOff[2], bsrc + 32);
        CP_ASYNC16(so + bOff[3], bsrc + 48);
        CP_COMMIT();
    };

    // ---- fragment addresses (stage-relative)
    const int rr = lane & 15, cc = lane >> 4;
    const uint32_t aswz = (uint32_t)((cc ^ ((rr >> 2) & 1)) << 4);
    uint32_t aAddr[4];
    #pragma unroll
    for (int mi = 0; mi < 4; ++mi)
        aAddr[mi] = (uint32_t)((wm * 64 + mi * 16 + rr) * 32) + aswz;
    const int kk = ((lane >> 3) & 1) * 8 + (lane & 7);
    const int j2 = lane >> 4;
    uint32_t bAddr[4];
    #pragma unroll
    for (int p = 0; p < 4; ++p)
        bAddr[p] = (uint32_t)(8192 + kk * 256 + (((wn * 8 + p * 2 + j2) ^ (lane & 7)) << 4));

    float acc[4][8][4];
    #pragma unroll
    for (int mi = 0; mi < 4; ++mi)
        #pragma unroll
        for (int ni = 0; ni < 8; ++ni)
            #pragma unroll
            for (int q = 0; q < 4; ++q) acc[mi][ni][q] = 0.f;

    load_stage(0); load_stage(1); load_stage(2);

    for (int kt = 0; kt < NKT; ++kt) {
        CP_WAIT(2);
        __syncthreads();
        if (kt + 3 < NKT) load_stage(kt + 3); else CP_COMMIT();

        const uint32_t sA = sbase + (uint32_t)((kt & (NSTAGE - 1)) * STAGE);
        // issue ALL fragment loads for both k16-halves up front (16 LDSM),
        // then 64 MMAs — LDSM latency buried under MMA issue.
        uint32_t a[2][4][4], b[2][8][2];
        #pragma unroll
        for (int s2 = 0; s2 < 2; ++s2) {
            #pragma unroll
            for (int mi = 0; mi < 4; ++mi)
                LDSM_X4(a[s2][mi], sA + s2 * 4096 + aAddr[mi]);
            #pragma unroll
            for (int p = 0; p < 4; ++p) {
                uint32_t t4[4];
                LDSM_X4T(t4, sA + s2 * 4096 + bAddr[p]);
                b[s2][2*p][0] = t4[0]; b[s2][2*p][1] = t4[1];
                b[s2][2*p+1][0] = t4[2]; b[s2][2*p+1][1] = t4[3];
            }
        }
        #pragma unroll
        for (int s2 = 0; s2 < 2; ++s2)
            #pragma unroll
            for (int mi = 0; mi < 4; ++mi)
                #pragma unroll
                for (int ni = 0; ni < 8; ++ni)
                    mma_f16(acc[mi][ni], a[s2][mi], b[s2][ni]);
    }

    // ---- epilogue: direct stores (R6 style; restage regressed)
    const int grp = lane >> 2, qid = lane & 3;
    #pragma unroll
    for (int mi = 0; mi < 4; ++mi) {
        const int r0 = m0 + wm * 64 + mi * 16 + grp;
        #pragma unroll
        for (int ni = 0; ni < 8; ++ni) {
            const int c = n0 + wn * 64 + ni * 8 + qid * 2;
            const float2 bv = *(const float2*)(bias + c);
            float v00 = acc[mi][ni][0] + bv.x;
            float v01 = acc[mi][ni][1] + bv.y;
            float v10 = acc[mi][ni][2] + bv.x;
            float v11 = acc[mi][ni][3] + bv.y;
            if (GATHER) {
                v00 = gelu_t(v00); v01 = gelu_t(v01);
                v10 = gelu_t(v10); v11 = gelu_t(v11);
                if (r0 < cnt) {
                    __half2 h = __floats2half2_rn(v00, v01);
                    *(__half2*)(g_hf + ((size_t)e * TKN + r0) * NOUT + c) = h;
                }
                if (r0 + 8 < cnt) {
                    __half2 h = __floats2half2_rn(v10, v11);
                    *(__half2*)(g_hf + ((size_t)e * TKN + r0 + 8) * NOUT + c) = h;
                }
            } else {
                if (r0 < cnt)
                    *(float2*)(g_o2 + ((size_t)e * TKN + r0) * NOUT + c) = make_float2(v00, v01);
                if (r0 + 8 < cnt)
                    *(float2*)(g_o2 + ((size_t)e * TKN + r0 + 8) * NOUT + c) = make_float2(v10, v11);
            }
        }
    }
}

// out = x + shared + w0*routed0 + w1*routed1
__global__ void combine_kernel(const float* __restrict__ x, float* __restrict__ out) {
    int t = blockIdx.x, tid = threadIdx.x;
    int e0 = g_re[2*t],     s0 = g_rs[2*t];
    int e1 = g_re[2*t + 1], s1 = g_rs[2*t + 1];
    float w0 = g_rw[2*t], w1 = g_rw[2*t + 1];
    const float4* xp  = (const float4*)(x + (size_t)t * DIM);
    const float4* shp = (const float4*)(g_o2 + ((size_t)NEXP * TKN + t) * DIM);
    const float4* r0p = (const float4*)(g_o2 + ((size_t)e0 * TKN + s0) * DIM);
    const float4* r1p = (const float4*)(g_o2 + ((size_t)e1 * TKN + s1) * DIM);
    float4 xv = xp[tid], sv = shp[tid], a = r0p[tid], b = r1p[tid];
    float4 o;
    o.x = xv.x + sv.x + w0 * a.x + w1 * b.x;
    o.y = xv.y + sv.y + w0 * a.y + w1 * b.y;
    o.z = xv.z + sv.z + w0 * a.z + w1 * b.z;
    o.w = xv.w + sv.w + w0 * a.w + w1 * b.w;
    ((float4*)(out + (size_t)t * DIM))[tid] = o;
}

// ---------------------------------------------------------------------------
extern "C" void kernel_launch(void* const* d_in, const int* in_sizes, int n_in,
                              void* d_out, int out_size) {
    const float* x   = (const float*)d_in[0];
    const float* tc  = (const float*)d_in[1];
    const float* aw  = (const float*)d_in[2];
    const float* ab  = (const float*)d_in[3];
    const float* gw  = (const float*)d_in[4];
    const float* w1  = (const float*)d_in[5];
    const float* b1  = (const float*)d_in[6];
    const float* w2  = (const float*)d_in[7];
    const float* b2  = (const float*)d_in[8];
    const float* sw1 = (const float*)d_in[9];
    const float* sb1 = (const float*)d_in[10];
    const float* sw2 = (const float*)d_in[11];
    const float* sb2 = (const float*)d_in[12];
    float* out = (float*)d_out;

    cudaFuncSetAttribute(moe_hgemm<true >, cudaFuncAttributeMaxDynamicSharedMemorySize, SMEM_BYTES);
    cudaFuncSetAttribute(moe_hgemm<false>, cudaFuncAttributeMaxDynamicSharedMemorySize, SMEM_BYTES);

    void* p;
    cudaGetSymbolAddress(&p, g_w1h);  uint2* w1h = (uint2*)p;
    cudaGetSymbolAddress(&p, g_w2h);  uint2* w2h = (uint2*)p;
    cudaGetSymbolAddress(&p, g_sw1h); uint2* s1h = (uint2*)p;
    cudaGetSymbolAddress(&p, g_sw2h); uint2* s2h = (uint2*)p;

    cond_kernel<<<dim3((2 * DIM) / 256, NBATCH), 256>>>(tc, aw, ab);     // user #0 (+init)
    adaln_route<<<TKN, 256>>>(x, gw);                                    // user #1
    {
        long total4 = 2L * NEXP * DIM * HID / 4 + 2L * DIM * HID / 4;
        f2h_all<<<(int)((total4 + 255) / 256), 256>>>(                   // user #2
            (const float4*)w1, (const float4*)w2, (const float4*)sw1, (const float4*)sw2,
            w1h, w2h, s1h, s2h);
    }
    moe_hgemm<true ><<<dim3(HID / BN, TKN / BM, 9), 128, SMEM_BYTES>>>(  // user #3 (profiled)
        (const __half*)w1h, (const __half*)s1h, b1, sb1);
    moe_hgemm<false><<<dim3(DIM / BN, TKN / BM, 9), 128, SMEM_BYTES>>>(  // user #4
        (const __half*)w2h, (const __half*)s2h, b2, sb2);
    combine_kernel<<<TKN, 256>>>(x, out);                                // user #5
}